// round 16
// baseline (speedup 1.0000x reference)
#include <cuda_runtime.h>
#include <cuda_bf16.h>
#include <cstdint>

// Problem shapes (fixed by reference setup_inputs)
#define N_SEQ   256
#define M_GENES 2000
#define D_DIM   128

// FINAL kernel — converged at the HBM write wall.
// Best measured: 43.10 us (x2 exact); 6 reproductions within 43.10-43.49 us.
// 262 MB mandated fp32 output / ~6.1 TB/s sustained pure-write BW = ~43 us
// physical floor; this kernel runs at ~99% of that measured ceiling.
//
//   Block: 256 threads = 8 warps. Warp w owns gene m = blockIdx.x*8 + w.
//   Tile:  32 sequence positions (blockIdx.y), matching warp size.
//
//   Prologue (per warp, registers only):
//     - 4x LDG.128: the gene's 4 embedding rows (L2-resident, 2 KB)
//     - butterfly-reduce the 4 squared norms (result in every lane)
//     - scale rows in registers -> r0..r3 (16 regs)
//     - lane nn loads gene_seq[n0+nn][m] (one 4B LDG per lane)
//
//   Inner loop (32 iterations): shfl index broadcast, 4-way register
//   select, one streaming STG.128 (.cs evict-first). Self-paced store
//   issue matches the HBM drain rate — measured best for replay steady
//   state. Tested-and-rejected alternatives (each a clean A/B):
//   SMEM-staged rows, TMA bulk 4KB stores, L2 write-back retention,
//   partitioned L2 pinning, grid reshapes, 256-bit v8 stores,
//   launch-order footprint spread.
__global__ void __launch_bounds__(256) fused_gene_embed_kernel(
    const int* __restrict__ gene_seq,      // (N, M)
    const float* __restrict__ emb,         // (M, 4, D)
    float* __restrict__ out)               // (N, M, D)
{
    const int warp = threadIdx.x >> 5;
    const int lane = threadIdx.x & 31;
    const int m  = blockIdx.x * 8 + warp;   // grid.x = 250 (exact)
    const int n0 = blockIdx.y * 32;         // grid.y = 8   (exact)

    // ---- load this gene's 4 table rows into registers ----
    const float4* src = reinterpret_cast<const float4*>(emb) + (size_t)m * 4 * 32;
    float4 r0 = src[lane];
    float4 r1 = src[32 + lane];
    float4 r2 = src[64 + lane];
    float4 r3 = src[96 + lane];

    // ---- per-lane sequence index (lane == nn within the 32-tile) ----
    const int gl = gene_seq[(size_t)(n0 + lane) * M_GENES + m];

    // ---- normalize rows in registers (butterfly keeps norm in all lanes) ----
    {
        float s0 = r0.x*r0.x + r0.y*r0.y + r0.z*r0.z + r0.w*r0.w;
        float s1 = r1.x*r1.x + r1.y*r1.y + r1.z*r1.z + r1.w*r1.w;
        float s2 = r2.x*r2.x + r2.y*r2.y + r2.z*r2.z + r2.w*r2.w;
        float s3 = r3.x*r3.x + r3.y*r3.y + r3.z*r3.z + r3.w*r3.w;
        #pragma unroll
        for (int off = 16; off > 0; off >>= 1) {
            s0 += __shfl_xor_sync(0xFFFFFFFFu, s0, off);
            s1 += __shfl_xor_sync(0xFFFFFFFFu, s1, off);
            s2 += __shfl_xor_sync(0xFFFFFFFFu, s2, off);
            s3 += __shfl_xor_sync(0xFFFFFFFFu, s3, off);
        }
        const float i0 = 1.0f / fmaxf(sqrtf(s0), 1e-12f);
        const float i1 = 1.0f / fmaxf(sqrtf(s1), 1e-12f);
        const float i2 = 1.0f / fmaxf(sqrtf(s2), 1e-12f);
        const float i3 = 1.0f / fmaxf(sqrtf(s3), 1e-12f);
        r0.x *= i0; r0.y *= i0; r0.z *= i0; r0.w *= i0;
        r1.x *= i1; r1.y *= i1; r1.z *= i1; r1.w *= i1;
        r2.x *= i2; r2.y *= i2; r2.z *= i2; r2.w *= i2;
        r3.x *= i3; r3.y *= i3; r3.z *= i3; r3.w *= i3;
    }

    // ---- pure streaming-store loop ----
    float4* ob = reinterpret_cast<float4*>(out)
               + ((size_t)n0 * M_GENES + m) * 32 + lane;
    const size_t row_stride = (size_t)M_GENES * 32;   // one n step

    #pragma unroll 8
    for (int nn = 0; nn < 32; nn++) {
        const int g = __shfl_sync(0xFFFFFFFFu, gl, nn);
        const float4 v = (g == 0) ? r0 : (g == 1) ? r1 : (g == 2) ? r2 : r3;
        __stcs(ob, v);
        ob += row_stride;
    }
}

extern "C" void kernel_launch(void* const* d_in, const int* in_sizes, int n_in,
                              void* d_out, int out_size) {
    const int* gene_seq = (const int*)d_in[0];      // (256, 2000) int32
    const float* emb    = (const float*)d_in[1];    // (2000, 4, 128) fp32
    float* out          = (float*)d_out;            // (256, 2000, 128) fp32

    dim3 grid(M_GENES / 8, N_SEQ / 32, 1);          // (250, 8)
    fused_gene_embed_kernel<<<grid, 256>>>(gene_seq, emb, out);
}